// round 4
// baseline (speedup 1.0000x reference)
#include <cuda_runtime.h>

#define BB 4
#define SS 1024
#define HH 8
#define DD 64
#define DM 512
#define BH (BB*HH)

// ---------------- scratch (device globals; never passed from host) ---------
__device__ float g_Q[BH*SS*DD];   // (b,h,s,d)
__device__ float g_K[BH*SS*DD];
__device__ float g_V[BH*SS*DD];
__device__ float g_O[BB*SS*DM];   // (b,s,h*64+d) AV output
__device__ float g_Y[BB*SS*DM];   // pre-LN
__device__ float g_W0[DD], g_W1[DD], g_Wc[DD];

// ---------------- fold relative-position MLP into affine map ---------------
__global__ void k_wc(const float* __restrict__ rp_w1, const float* __restrict__ rp_b1,
                     const float* __restrict__ rp_w2, const float* __restrict__ rp_b2) {
    int d = threadIdx.x;
    if (d < 64) {
        float w0 = 0.f, w1 = 0.f, c = 0.f;
        #pragma unroll 8
        for (int j = 0; j < 64; j++) {
            float w2 = rp_w2[d*64 + j];
            w0 += w2 * rp_w1[j*2 + 0];
            w1 += w2 * rp_w1[j*2 + 1];
            c  += w2 * rp_b1[j];
        }
        g_W0[d] = w0;
        g_W1[d] = w1;
        g_Wc[d] = c + rp_b2[d];
    }
}

// ---------------- projection GEMM: C[m,n]=sum_k X[m,k]*W[n,k] -> (b,h,s,d) --
// SEL: 0->g_Q, 1->g_K, 2->g_V (device-side symbol selection; NEVER from host)
template<int SEL>
__global__ __launch_bounds__(256) void k_proj(const float* __restrict__ X,
                                              const float* __restrict__ W) {
    float* out = (SEL == 0) ? g_Q : (SEL == 1) ? g_K : g_V;
    __shared__ float sA[16][68];
    __shared__ float sB[16][68];
    int tid = threadIdx.x;
    int tx = tid & 15, ty = tid >> 4;
    int m0 = blockIdx.y * 64, n0 = blockIdx.x * 64;
    int lr = tid >> 2, ls = tid & 3;
    float acc[4][4] = {};
    for (int k0 = 0; k0 < 512; k0 += 16) {
        float4 a = *(const float4*)&X[(m0 + lr) * 512 + k0 + ls * 4];
        float4 b = *(const float4*)&W[(n0 + lr) * 512 + k0 + ls * 4];
        sA[ls*4+0][lr] = a.x; sA[ls*4+1][lr] = a.y; sA[ls*4+2][lr] = a.z; sA[ls*4+3][lr] = a.w;
        sB[ls*4+0][lr] = b.x; sB[ls*4+1][lr] = b.y; sB[ls*4+2][lr] = b.z; sB[ls*4+3][lr] = b.w;
        __syncthreads();
        #pragma unroll
        for (int kk = 0; kk < 16; kk++) {
            float4 av = *(const float4*)&sA[kk][ty*4];
            float4 bv = *(const float4*)&sB[kk][tx*4];
            float ar[4] = {av.x, av.y, av.z, av.w};
            float br[4] = {bv.x, bv.y, bv.z, bv.w};
            #pragma unroll
            for (int i = 0; i < 4; i++)
                #pragma unroll
                for (int j = 0; j < 4; j++)
                    acc[i][j] += ar[i] * br[j];
        }
        __syncthreads();
    }
    int h = n0 >> 6;
    int dbase = tx * 4;
    #pragma unroll
    for (int i = 0; i < 4; i++) {
        int m = m0 + ty * 4 + i;
        int b = m >> 10, s = m & 1023;
        float4 r = make_float4(acc[i][0], acc[i][1], acc[i][2], acc[i][3]);
        *(float4*)&out[((size_t)(b * HH + h) * SS + s) * DD + dbase] = r;
    }
}

// ---------------- logits: attn_logits[bh,q,k] -------------------------------
// 32q x 64k tile per block; static smem (40KB); 3 pre-scaled Q copies.
__global__ __launch_bounds__(256) void k_logits(const float* __restrict__ pos,
                                                float* __restrict__ attn) {
    __shared__ float sQ0[64][32];
    __shared__ float sQ1[64][32];
    __shared__ float sQ2[64][32];
    __shared__ float sK [64][64];
    int bh = blockIdx.z;
    int q0 = blockIdx.y * 32, k0 = blockIdx.x * 64;
    const float* Qb = g_Q + (size_t)bh * SS * DD;
    const float* Kb = g_K + (size_t)bh * SS * DD;
    int tid = threadIdx.x;

    // Q tile: 32 rows x 64 d, scaled by W0/W1/Wc, stored d-major
    {
        int qr = tid >> 3;          // 0..31
        int qc = tid & 7;           // 0..7
        #pragma unroll
        for (int cc = 0; cc < 2; cc++) {
            int c4 = cc * 8 + qc;   // float4 col 0..15
            float4 qv = *(const float4*)&Qb[(q0 + qr) * DD + c4 * 4];
            float qa[4] = {qv.x, qv.y, qv.z, qv.w};
            #pragma unroll
            for (int c = 0; c < 4; c++) {
                int d = c4 * 4 + c;
                sQ0[d][qr] = qa[c] * g_W0[d];
                sQ1[d][qr] = qa[c] * g_W1[d];
                sQ2[d][qr] = qa[c] * g_Wc[d];
            }
        }
        // K tile: 64 rows x 64 d, d-major
        int kr = tid >> 2;          // 0..63
        int kc = tid & 3;           // 0..3
        #pragma unroll
        for (int cc = 0; cc < 4; cc++) {
            int c4 = cc * 4 + kc;   // 0..15
            float4 kv = *(const float4*)&Kb[(k0 + kr) * DD + c4 * 4];
            float ka[4] = {kv.x, kv.y, kv.z, kv.w};
            #pragma unroll
            for (int c = 0; c < 4; c++) sK[c4 * 4 + c][kr] = ka[c];
        }
    }
    __syncthreads();

    int tx = tid & 15, ty = tid >> 4;   // tx: k-group, ty: q-group
    float s0[2][4] = {}, s1[2][4] = {}, s2[2][4] = {};
    #pragma unroll 8
    for (int d = 0; d < 64; d++) {
        float2 a0 = *(const float2*)&sQ0[d][ty * 2];
        float2 a1 = *(const float2*)&sQ1[d][ty * 2];
        float2 a2 = *(const float2*)&sQ2[d][ty * 2];
        float4 bk = *(const float4*)&sK [d][tx * 4];
        float b[4] = {bk.x, bk.y, bk.z, bk.w};
        float r0[2] = {a0.x, a0.y};
        float r1[2] = {a1.x, a1.y};
        float r2[2] = {a2.x, a2.y};
        #pragma unroll
        for (int i = 0; i < 2; i++)
            #pragma unroll
            for (int j = 0; j < 4; j++) {
                s0[i][j] += r0[i] * b[j];
                s1[i][j] += r1[i] * b[j];
                s2[i][j] += r2[i] * b[j];
            }
    }

    const float inv_t = 0.125f;   // 1/TEMPERATURE
    #pragma unroll
    for (int i = 0; i < 2; i++) {
        int q = q0 + ty * 2 + i;
        const float2* prow = (const float2*)pos + (size_t)q * SS + k0 + tx * 4;
        float v[4];
        #pragma unroll
        for (int j = 0; j < 4; j++) {
            float2 p = prow[j];
            v[j] = (s0[i][j] * p.x + s1[i][j] * p.y + s2[i][j]) * inv_t;
        }
        *(float4*)&attn[((size_t)(bh * SS + q)) * SS + k0 + tx * 4] =
            make_float4(v[0], v[1], v[2], v[3]);
    }
}

// ---------------- row softmax over k (in place on attn buffer) --------------
__device__ __forceinline__ float warpMax(float v) {
    #pragma unroll
    for (int o = 16; o; o >>= 1) v = fmaxf(v, __shfl_xor_sync(0xffffffffu, v, o));
    return v;
}
__device__ __forceinline__ float warpSum(float v) {
    #pragma unroll
    for (int o = 16; o; o >>= 1) v += __shfl_xor_sync(0xffffffffu, v, o);
    return v;
}

__global__ __launch_bounds__(256) void k_softmax(float* __restrict__ attn) {
    size_t row = blockIdx.x;
    float* p = attn + row * SS;
    int tid = threadIdx.x;
    float4 v = *(const float4*)(p + tid * 4);
    __shared__ float r1[8], r2[8];

    float mx = fmaxf(fmaxf(v.x, v.y), fmaxf(v.z, v.w));
    mx = warpMax(mx);
    if ((tid & 31) == 0) r1[tid >> 5] = mx;
    __syncthreads();
    float bmax = r1[0];
    #pragma unroll
    for (int i = 1; i < 8; i++) bmax = fmaxf(bmax, r1[i]);

    float e0 = __expf(v.x - bmax), e1 = __expf(v.y - bmax);
    float e2 = __expf(v.z - bmax), e3 = __expf(v.w - bmax);
    float s = (e0 + e1) + (e2 + e3);
    s = warpSum(s);
    if ((tid & 31) == 0) r2[tid >> 5] = s;
    __syncthreads();
    float total = 0.f;
    #pragma unroll
    for (int i = 0; i < 8; i++) total += r2[i];
    float inv = 1.0f / total;
    *(float4*)(p + tid * 4) = make_float4(e0 * inv, e1 * inv, e2 * inv, e3 * inv);
}

// ---------------- AV GEMM: O[q,d] = sum_k P[q,k] V[k,d] per (b,h) -----------
__global__ __launch_bounds__(256) void k_av(const float* __restrict__ attn) {
    __shared__ float sP[16][68];
    __shared__ float sV[16][64];
    int bh = blockIdx.y;
    int q0 = blockIdx.x * 64;
    const float* Prow = attn + (size_t)bh * SS * SS;
    const float* Vb = g_V + (size_t)bh * SS * DD;
    int tid = threadIdx.x;
    int tx = tid & 15, ty = tid >> 4;
    int lr = tid >> 2, ls = tid & 3;
    int vr = tid >> 4, vs = tid & 15;
    float acc[4][4] = {};
    for (int k0 = 0; k0 < SS; k0 += 16) {
        float4 pv = *(const float4*)&Prow[(size_t)(q0 + lr) * SS + k0 + ls * 4];
        sP[ls*4+0][lr] = pv.x; sP[ls*4+1][lr] = pv.y; sP[ls*4+2][lr] = pv.z; sP[ls*4+3][lr] = pv.w;
        *(float4*)&sV[vr][vs * 4] = *(const float4*)&Vb[(k0 + vr) * DD + vs * 4];
        __syncthreads();
        #pragma unroll
        for (int kk = 0; kk < 16; kk++) {
            float4 av = *(const float4*)&sP[kk][ty*4];
            float4 bv = *(const float4*)&sV[kk][tx*4];
            float ar[4] = {av.x, av.y, av.z, av.w};
            float br[4] = {bv.x, bv.y, bv.z, bv.w};
            #pragma unroll
            for (int i = 0; i < 4; i++)
                #pragma unroll
                for (int j = 0; j < 4; j++)
                    acc[i][j] += ar[i] * br[j];
        }
        __syncthreads();
    }
    int b = bh >> 3, h = bh & 7;
    #pragma unroll
    for (int i = 0; i < 4; i++) {
        int q = q0 + ty * 4 + i;
        float4 r = make_float4(acc[i][0], acc[i][1], acc[i][2], acc[i][3]);
        *(float4*)&g_O[((size_t)(b * SS + q)) * DM + h * 64 + tx * 4] = r;
    }
}

// ---------------- fc GEMM + residual: g_Y = g_O @ w_fc^T + resid ------------
__global__ __launch_bounds__(256) void k_fc(const float* __restrict__ W,
                                            const float* __restrict__ resid) {
    const float* X = g_O;
    float* out = g_Y;
    __shared__ float sA[16][68];
    __shared__ float sB[16][68];
    int tid = threadIdx.x;
    int tx = tid & 15, ty = tid >> 4;
    int m0 = blockIdx.y * 64, n0 = blockIdx.x * 64;
    int lr = tid >> 2, ls = tid & 3;
    float acc[4][4] = {};
    for (int k0 = 0; k0 < 512; k0 += 16) {
        float4 a = *(const float4*)&X[(m0 + lr) * 512 + k0 + ls * 4];
        float4 b = *(const float4*)&W[(n0 + lr) * 512 + k0 + ls * 4];
        sA[ls*4+0][lr] = a.x; sA[ls*4+1][lr] = a.y; sA[ls*4+2][lr] = a.z; sA[ls*4+3][lr] = a.w;
        sB[ls*4+0][lr] = b.x; sB[ls*4+1][lr] = b.y; sB[ls*4+2][lr] = b.z; sB[ls*4+3][lr] = b.w;
        __syncthreads();
        #pragma unroll
        for (int kk = 0; kk < 16; kk++) {
            float4 av = *(const float4*)&sA[kk][ty*4];
            float4 bv = *(const float4*)&sB[kk][tx*4];
            float ar[4] = {av.x, av.y, av.z, av.w};
            float br[4] = {bv.x, bv.y, bv.z, bv.w};
            #pragma unroll
            for (int i = 0; i < 4; i++)
                #pragma unroll
                for (int j = 0; j < 4; j++)
                    acc[i][j] += ar[i] * br[j];
        }
        __syncthreads();
    }
    #pragma unroll
    for (int i = 0; i < 4; i++) {
        int m = m0 + ty * 4 + i;
        float4 rs = *(const float4*)&resid[(size_t)m * 512 + n0 + tx * 4];
        float4 r = make_float4(acc[i][0] + rs.x, acc[i][1] + rs.y,
                               acc[i][2] + rs.z, acc[i][3] + rs.w);
        *(float4*)&out[(size_t)m * 512 + n0 + tx * 4] = r;
    }
}

// ---------------- LayerNorm over 512 ----------------------------------------
__global__ __launch_bounds__(128) void k_ln(const float* __restrict__ g,
                                            const float* __restrict__ bta,
                                            float* __restrict__ out) {
    size_t row = blockIdx.x;
    const float* y = g_Y + row * 512;
    int tid = threadIdx.x;
    float4 v = *(const float4*)(y + tid * 4);
    float s = (v.x + v.y) + (v.z + v.w);
    float ss = v.x * v.x + v.y * v.y + v.z * v.z + v.w * v.w;
    __shared__ float r1[4], r2[4];
    s = warpSum(s);
    ss = warpSum(ss);
    if ((tid & 31) == 0) { r1[tid >> 5] = s; r2[tid >> 5] = ss; }
    __syncthreads();
    float ts = 0.f, tss = 0.f;
    #pragma unroll
    for (int i = 0; i < 4; i++) { ts += r1[i]; tss += r2[i]; }
    float mu = ts * (1.0f / 512.0f);
    float var = tss * (1.0f / 512.0f) - mu * mu;
    float rstd = rsqrtf(var + 1e-6f);
    float4 gg = *(const float4*)(g + tid * 4);
    float4 bb = *(const float4*)(bta + tid * 4);
    float4 r;
    r.x = (v.x - mu) * rstd * gg.x + bb.x;
    r.y = (v.y - mu) * rstd * gg.y + bb.y;
    r.z = (v.z - mu) * rstd * gg.z + bb.z;
    r.w = (v.w - mu) * rstd * gg.w + bb.w;
    *(float4*)(out + row * 512 + tid * 4) = r;
}

// ---------------- launch ----------------------------------------------------
extern "C" void kernel_launch(void* const* d_in, const int* in_sizes, int n_in,
                              void* d_out, int out_size) {
    const float* q     = (const float*)d_in[0];
    const float* k     = (const float*)d_in[1];
    const float* v     = (const float*)d_in[2];
    const float* pos   = (const float*)d_in[3];
    const float* w_qs  = (const float*)d_in[4];
    const float* w_ks  = (const float*)d_in[5];
    const float* w_vs  = (const float*)d_in[6];
    const float* w_fc  = (const float*)d_in[7];
    const float* rp_w1 = (const float*)d_in[8];
    const float* rp_b1 = (const float*)d_in[9];
    const float* rp_w2 = (const float*)d_in[10];
    const float* rp_b2 = (const float*)d_in[11];
    const float* ln_g  = (const float*)d_in[12];
    const float* ln_b  = (const float*)d_in[13];

    float* out  = (float*)d_out;
    float* attn = out + (size_t)BB * SS * DM;   // output 0: out, output 1: attn

    k_wc<<<1, 64>>>(rp_w1, rp_b1, rp_w2, rp_b2);

    dim3 gp(DM / 64, (BB * SS) / 64);
    k_proj<0><<<gp, 256>>>(q, w_qs);
    k_proj<1><<<gp, 256>>>(k, w_ks);
    k_proj<2><<<gp, 256>>>(v, w_vs);

    dim3 gl(SS / 64, SS / 32, BH);
    k_logits<<<gl, 256>>>(pos, attn);

    k_softmax<<<BH * SS, 256>>>(attn);

    dim3 ga(SS / 64, BH);
    k_av<<<ga, 256>>>(attn);

    k_fc<<<gp, 256>>>(w_fc, q);

    k_ln<<<BB * SS, 128>>>(ln_g, ln_b, out);
}

// round 5
// speedup vs baseline: 1.0001x; 1.0001x over previous
#include <cuda_runtime.h>

#define BB 4
#define SS 1024
#define HH 8
#define DD 64
#define DM 512
#define BH (BB*HH)

// ---------------- scratch (device globals; never passed from host) ---------
__device__ float g_Q[BH*SS*DD];   // (b,h,s,d)
__device__ float g_K[BH*SS*DD];
__device__ float g_V[BH*SS*DD];
__device__ float g_O[BB*SS*DM];   // (b,s,h*64+d) AV output
__device__ float g_Y[BB*SS*DM];   // pre-LN
__device__ float g_W0[DD], g_W1[DD], g_Wc[DD];

// ---------------- fold relative-position MLP into affine map ---------------
__global__ void k_wc(const float* __restrict__ rp_w1, const float* __restrict__ rp_b1,
                     const float* __restrict__ rp_w2, const float* __restrict__ rp_b2) {
    int d = threadIdx.x;
    if (d < 64) {
        float w0 = 0.f, w1 = 0.f, c = 0.f;
        #pragma unroll 8
        for (int j = 0; j < 64; j++) {
            float w2 = rp_w2[d*64 + j];
            w0 += w2 * rp_w1[j*2 + 0];
            w1 += w2 * rp_w1[j*2 + 1];
            c  += w2 * rp_b1[j];
        }
        g_W0[d] = w0;
        g_W1[d] = w1;
        g_Wc[d] = c + rp_b2[d];
    }
}

// ---------------- projection GEMM: C[m,n]=sum_k X[m,k]*W[n,k] -> (b,h,s,d) --
// SEL: 0->g_Q, 1->g_K, 2->g_V (device-side symbol selection; NEVER from host)
template<int SEL>
__global__ __launch_bounds__(256) void k_proj(const float* __restrict__ X,
                                              const float* __restrict__ W) {
    float* out = (SEL == 0) ? g_Q : (SEL == 1) ? g_K : g_V;
    __shared__ float sA[16][68];
    __shared__ float sB[16][68];
    int tid = threadIdx.x;
    int tx = tid & 15, ty = tid >> 4;
    int m0 = blockIdx.y * 64, n0 = blockIdx.x * 64;
    int lr = tid >> 2, ls = tid & 3;
    float acc[4][4] = {};
    for (int k0 = 0; k0 < 512; k0 += 16) {
        float4 a = *(const float4*)&X[(m0 + lr) * 512 + k0 + ls * 4];
        float4 b = *(const float4*)&W[(n0 + lr) * 512 + k0 + ls * 4];
        sA[ls*4+0][lr] = a.x; sA[ls*4+1][lr] = a.y; sA[ls*4+2][lr] = a.z; sA[ls*4+3][lr] = a.w;
        sB[ls*4+0][lr] = b.x; sB[ls*4+1][lr] = b.y; sB[ls*4+2][lr] = b.z; sB[ls*4+3][lr] = b.w;
        __syncthreads();
        #pragma unroll
        for (int kk = 0; kk < 16; kk++) {
            float4 av = *(const float4*)&sA[kk][ty*4];
            float4 bv = *(const float4*)&sB[kk][tx*4];
            float ar[4] = {av.x, av.y, av.z, av.w};
            float br[4] = {bv.x, bv.y, bv.z, bv.w};
            #pragma unroll
            for (int i = 0; i < 4; i++)
                #pragma unroll
                for (int j = 0; j < 4; j++)
                    acc[i][j] += ar[i] * br[j];
        }
        __syncthreads();
    }
    int h = n0 >> 6;
    int dbase = tx * 4;
    #pragma unroll
    for (int i = 0; i < 4; i++) {
        int m = m0 + ty * 4 + i;
        int b = m >> 10, s = m & 1023;
        float4 r = make_float4(acc[i][0], acc[i][1], acc[i][2], acc[i][3]);
        *(float4*)&out[((size_t)(b * HH + h) * SS + s) * DD + dbase] = r;
    }
}

// ---------------- logits: attn_logits[bh,q,k] -------------------------------
// 32q x 64k tile per block; static smem (40KB); 3 pre-scaled Q copies.
__global__ __launch_bounds__(256) void k_logits(const float* __restrict__ pos,
                                                float* __restrict__ attn) {
    __shared__ float sQ0[64][32];
    __shared__ float sQ1[64][32];
    __shared__ float sQ2[64][32];
    __shared__ float sK [64][64];
    int bh = blockIdx.z;
    int q0 = blockIdx.y * 32, k0 = blockIdx.x * 64;
    const float* Qb = g_Q + (size_t)bh * SS * DD;
    const float* Kb = g_K + (size_t)bh * SS * DD;
    int tid = threadIdx.x;

    // Q tile: 32 rows x 64 d, scaled by W0/W1/Wc, stored d-major
    {
        int qr = tid >> 3;          // 0..31
        int qc = tid & 7;           // 0..7
        #pragma unroll
        for (int cc = 0; cc < 2; cc++) {
            int c4 = cc * 8 + qc;   // float4 col 0..15
            float4 qv = *(const float4*)&Qb[(q0 + qr) * DD + c4 * 4];
            float qa[4] = {qv.x, qv.y, qv.z, qv.w};
            #pragma unroll
            for (int c = 0; c < 4; c++) {
                int d = c4 * 4 + c;
                sQ0[d][qr] = qa[c] * g_W0[d];
                sQ1[d][qr] = qa[c] * g_W1[d];
                sQ2[d][qr] = qa[c] * g_Wc[d];
            }
        }
        // K tile: 64 rows x 64 d, d-major
        int kr = tid >> 2;          // 0..63
        int kc = tid & 3;           // 0..3
        #pragma unroll
        for (int cc = 0; cc < 4; cc++) {
            int c4 = cc * 4 + kc;   // 0..15
            float4 kv = *(const float4*)&Kb[(k0 + kr) * DD + c4 * 4];
            float ka[4] = {kv.x, kv.y, kv.z, kv.w};
            #pragma unroll
            for (int c = 0; c < 4; c++) sK[c4 * 4 + c][kr] = ka[c];
        }
    }
    __syncthreads();

    int tx = tid & 15, ty = tid >> 4;   // tx: k-group, ty: q-group
    float s0[2][4] = {}, s1[2][4] = {}, s2[2][4] = {};
    #pragma unroll 8
    for (int d = 0; d < 64; d++) {
        float2 a0 = *(const float2*)&sQ0[d][ty * 2];
        float2 a1 = *(const float2*)&sQ1[d][ty * 2];
        float2 a2 = *(const float2*)&sQ2[d][ty * 2];
        float4 bk = *(const float4*)&sK [d][tx * 4];
        float b[4] = {bk.x, bk.y, bk.z, bk.w};
        float r0[2] = {a0.x, a0.y};
        float r1[2] = {a1.x, a1.y};
        float r2[2] = {a2.x, a2.y};
        #pragma unroll
        for (int i = 0; i < 2; i++)
            #pragma unroll
            for (int j = 0; j < 4; j++) {
                s0[i][j] += r0[i] * b[j];
                s1[i][j] += r1[i] * b[j];
                s2[i][j] += r2[i] * b[j];
            }
    }

    const float inv_t = 0.125f;   // 1/TEMPERATURE
    #pragma unroll
    for (int i = 0; i < 2; i++) {
        int q = q0 + ty * 2 + i;
        const float2* prow = (const float2*)pos + (size_t)q * SS + k0 + tx * 4;
        float v[4];
        #pragma unroll
        for (int j = 0; j < 4; j++) {
            float2 p = prow[j];
            v[j] = (s0[i][j] * p.x + s1[i][j] * p.y + s2[i][j]) * inv_t;
        }
        *(float4*)&attn[((size_t)(bh * SS + q)) * SS + k0 + tx * 4] =
            make_float4(v[0], v[1], v[2], v[3]);
    }
}

// ---------------- row softmax over k (in place on attn buffer) --------------
__device__ __forceinline__ float warpMax(float v) {
    #pragma unroll
    for (int o = 16; o; o >>= 1) v = fmaxf(v, __shfl_xor_sync(0xffffffffu, v, o));
    return v;
}
__device__ __forceinline__ float warpSum(float v) {
    #pragma unroll
    for (int o = 16; o; o >>= 1) v += __shfl_xor_sync(0xffffffffu, v, o);
    return v;
}

__global__ __launch_bounds__(256) void k_softmax(float* __restrict__ attn) {
    size_t row = blockIdx.x;
    float* p = attn + row * SS;
    int tid = threadIdx.x;
    float4 v = *(const float4*)(p + tid * 4);
    __shared__ float r1[8], r2[8];

    float mx = fmaxf(fmaxf(v.x, v.y), fmaxf(v.z, v.w));
    mx = warpMax(mx);
    if ((tid & 31) == 0) r1[tid >> 5] = mx;
    __syncthreads();
    float bmax = r1[0];
    #pragma unroll
    for (int i = 1; i < 8; i++) bmax = fmaxf(bmax, r1[i]);

    float e0 = __expf(v.x - bmax), e1 = __expf(v.y - bmax);
    float e2 = __expf(v.z - bmax), e3 = __expf(v.w - bmax);
    float s = (e0 + e1) + (e2 + e3);
    s = warpSum(s);
    if ((tid & 31) == 0) r2[tid >> 5] = s;
    __syncthreads();
    float total = 0.f;
    #pragma unroll
    for (int i = 0; i < 8; i++) total += r2[i];
    float inv = 1.0f / total;
    *(float4*)(p + tid * 4) = make_float4(e0 * inv, e1 * inv, e2 * inv, e3 * inv);
}

// ---------------- AV GEMM: O[q,d] = sum_k P[q,k] V[k,d] per (b,h) -----------
__global__ __launch_bounds__(256) void k_av(const float* __restrict__ attn) {
    __shared__ float sP[16][68];
    __shared__ float sV[16][64];
    int bh = blockIdx.y;
    int q0 = blockIdx.x * 64;
    const float* Prow = attn + (size_t)bh * SS * SS;
    const float* Vb = g_V + (size_t)bh * SS * DD;
    int tid = threadIdx.x;
    int tx = tid & 15, ty = tid >> 4;
    int lr = tid >> 2, ls = tid & 3;
    int vr = tid >> 4, vs = tid & 15;
    float acc[4][4] = {};
    for (int k0 = 0; k0 < SS; k0 += 16) {
        float4 pv = *(const float4*)&Prow[(size_t)(q0 + lr) * SS + k0 + ls * 4];
        sP[ls*4+0][lr] = pv.x; sP[ls*4+1][lr] = pv.y; sP[ls*4+2][lr] = pv.z; sP[ls*4+3][lr] = pv.w;
        *(float4*)&sV[vr][vs * 4] = *(const float4*)&Vb[(k0 + vr) * DD + vs * 4];
        __syncthreads();
        #pragma unroll
        for (int kk = 0; kk < 16; kk++) {
            float4 av = *(const float4*)&sP[kk][ty*4];
            float4 bv = *(const float4*)&sV[kk][tx*4];
            float ar[4] = {av.x, av.y, av.z, av.w};
            float br[4] = {bv.x, bv.y, bv.z, bv.w};
            #pragma unroll
            for (int i = 0; i < 4; i++)
                #pragma unroll
                for (int j = 0; j < 4; j++)
                    acc[i][j] += ar[i] * br[j];
        }
        __syncthreads();
    }
    int b = bh >> 3, h = bh & 7;
    #pragma unroll
    for (int i = 0; i < 4; i++) {
        int q = q0 + ty * 4 + i;
        float4 r = make_float4(acc[i][0], acc[i][1], acc[i][2], acc[i][3]);
        *(float4*)&g_O[((size_t)(b * SS + q)) * DM + h * 64 + tx * 4] = r;
    }
}

// ---------------- fc GEMM + residual: g_Y = g_O @ w_fc^T + resid ------------
__global__ __launch_bounds__(256) void k_fc(const float* __restrict__ W,
                                            const float* __restrict__ resid) {
    const float* X = g_O;
    float* out = g_Y;
    __shared__ float sA[16][68];
    __shared__ float sB[16][68];
    int tid = threadIdx.x;
    int tx = tid & 15, ty = tid >> 4;
    int m0 = blockIdx.y * 64, n0 = blockIdx.x * 64;
    int lr = tid >> 2, ls = tid & 3;
    float acc[4][4] = {};
    for (int k0 = 0; k0 < 512; k0 += 16) {
        float4 a = *(const float4*)&X[(m0 + lr) * 512 + k0 + ls * 4];
        float4 b = *(const float4*)&W[(n0 + lr) * 512 + k0 + ls * 4];
        sA[ls*4+0][lr] = a.x; sA[ls*4+1][lr] = a.y; sA[ls*4+2][lr] = a.z; sA[ls*4+3][lr] = a.w;
        sB[ls*4+0][lr] = b.x; sB[ls*4+1][lr] = b.y; sB[ls*4+2][lr] = b.z; sB[ls*4+3][lr] = b.w;
        __syncthreads();
        #pragma unroll
        for (int kk = 0; kk < 16; kk++) {
            float4 av = *(const float4*)&sA[kk][ty*4];
            float4 bv = *(const float4*)&sB[kk][tx*4];
            float ar[4] = {av.x, av.y, av.z, av.w};
            float br[4] = {bv.x, bv.y, bv.z, bv.w};
            #pragma unroll
            for (int i = 0; i < 4; i++)
                #pragma unroll
                for (int j = 0; j < 4; j++)
                    acc[i][j] += ar[i] * br[j];
        }
        __syncthreads();
    }
    #pragma unroll
    for (int i = 0; i < 4; i++) {
        int m = m0 + ty * 4 + i;
        float4 rs = *(const float4*)&resid[(size_t)m * 512 + n0 + tx * 4];
        float4 r = make_float4(acc[i][0] + rs.x, acc[i][1] + rs.y,
                               acc[i][2] + rs.z, acc[i][3] + rs.w);
        *(float4*)&out[(size_t)m * 512 + n0 + tx * 4] = r;
    }
}

// ---------------- LayerNorm over 512 ----------------------------------------
__global__ __launch_bounds__(128) void k_ln(const float* __restrict__ g,
                                            const float* __restrict__ bta,
                                            float* __restrict__ out) {
    size_t row = blockIdx.x;
    const float* y = g_Y + row * 512;
    int tid = threadIdx.x;
    float4 v = *(const float4*)(y + tid * 4);
    float s = (v.x + v.y) + (v.z + v.w);
    float ss = v.x * v.x + v.y * v.y + v.z * v.z + v.w * v.w;
    __shared__ float r1[4], r2[4];
    s = warpSum(s);
    ss = warpSum(ss);
    if ((tid & 31) == 0) { r1[tid >> 5] = s; r2[tid >> 5] = ss; }
    __syncthreads();
    float ts = 0.f, tss = 0.f;
    #pragma unroll
    for (int i = 0; i < 4; i++) { ts += r1[i]; tss += r2[i]; }
    float mu = ts * (1.0f / 512.0f);
    float var = tss * (1.0f / 512.0f) - mu * mu;
    float rstd = rsqrtf(var + 1e-6f);
    float4 gg = *(const float4*)(g + tid * 4);
    float4 bb = *(const float4*)(bta + tid * 4);
    float4 r;
    r.x = (v.x - mu) * rstd * gg.x + bb.x;
    r.y = (v.y - mu) * rstd * gg.y + bb.y;
    r.z = (v.z - mu) * rstd * gg.z + bb.z;
    r.w = (v.w - mu) * rstd * gg.w + bb.w;
    *(float4*)(out + row * 512 + tid * 4) = r;
}

// ---------------- launch ----------------------------------------------------
extern "C" void kernel_launch(void* const* d_in, const int* in_sizes, int n_in,
                              void* d_out, int out_size) {
    const float* q     = (const float*)d_in[0];
    const float* k     = (const float*)d_in[1];
    const float* v     = (const float*)d_in[2];
    const float* pos   = (const float*)d_in[3];
    const float* w_qs  = (const float*)d_in[4];
    const float* w_ks  = (const float*)d_in[5];
    const float* w_vs  = (const float*)d_in[6];
    const float* w_fc  = (const float*)d_in[7];
    const float* rp_w1 = (const float*)d_in[8];
    const float* rp_b1 = (const float*)d_in[9];
    const float* rp_w2 = (const float*)d_in[10];
    const float* rp_b2 = (const float*)d_in[11];
    const float* ln_g  = (const float*)d_in[12];
    const float* ln_b  = (const float*)d_in[13];

    float* out  = (float*)d_out;
    float* attn = out + (size_t)BB * SS * DM;   // output 0: out, output 1: attn

    k_wc<<<1, 64>>>(rp_w1, rp_b1, rp_w2, rp_b2);

    dim3 gp(DM / 64, (BB * SS) / 64);
    k_proj<0><<<gp, 256>>>(q, w_qs);
    k_proj<1><<<gp, 256>>>(k, w_ks);
    k_proj<2><<<gp, 256>>>(v, w_vs);

    dim3 gl(SS / 64, SS / 32, BH);
    k_logits<<<gl, 256>>>(pos, attn);

    k_softmax<<<BH * SS, 256>>>(attn);

    dim3 ga(SS / 64, BH);
    k_av<<<ga, 256>>>(attn);

    k_fc<<<gp, 256>>>(w_fc, q);

    k_ln<<<BB * SS, 128>>>(ln_g, ln_b, out);
}